// round 6
// baseline (speedup 1.0000x reference)
#include <cuda_runtime.h>

// VecInt: scaling-and-squaring integration of a stationary velocity field.
// vec (1,3,160,192,160) fp32, nsteps=7.
//
// Round 6: MLP x2. Each thread (pair-lane) handles TWO voxels: (x,y,z) and
// (x,y,z+D/2). 8 independent corner gathers + 2 v-loads in flight per thread
// (vs 4+1) to test the latency-plateau hypothesis from R1/R3/R5 evidence.
// Pair-lane x-gather retained: even lane takes x0, odd lane x1; x-adjacent
// 32B corner pair lands in one instruction at adjacent lanes.
// Per-voxel arithmetic identical to R5 (same rel_err).

constexpr int D = 160;
constexpr int H = 192;
constexpr int W = 160;
constexpr int NVOX = D * H * W;          // 4,915,200
constexpr int NSTEPS = 7;
constexpr int ZHALF = D / 2;             // 80
constexpr int ZOFF  = ZHALF * H * W;     // voxel offset between the two z's

__device__ __align__(128) float4 g_bufA[NVOX];
__device__ __align__(128) float4 g_bufB[NVOX];

__global__ void __launch_bounds__(256)
scale_in_kernel(const float* __restrict__ in, float4* __restrict__ out)
{
    int i4 = blockIdx.x * 256 + threadIdx.x;   // handles voxels 4*i4 .. 4*i4+3
    const float s  = 1.0f / 128.0f;            // 1/2^7
    const float sx = s * 0.5f * (D - 1);
    const float sy = s * 0.5f * (H - 1);
    const float sz = s * 0.5f * (W - 1);

    float4 a = reinterpret_cast<const float4*>(in)[i4];             // ch z
    float4 b = reinterpret_cast<const float4*>(in + NVOX)[i4];      // ch y
    float4 c = reinterpret_cast<const float4*>(in + 2 * NVOX)[i4];  // ch x

    int base = i4 * 4;
    out[base + 0] = make_float4(a.x * sx, b.x * sy, c.x * sz, 0.0f);
    out[base + 1] = make_float4(a.y * sx, b.y * sy, c.y * sz, 0.0f);
    out[base + 2] = make_float4(a.z * sx, b.z * sy, c.z * sz, 0.0f);
    out[base + 3] = make_float4(a.w * sx, b.w * sy, c.w * sz, 0.0f);
}

struct Setup {
    int   r00, r01, r10, r11;   // gather addresses (this lane's x column)
    float Wy0, Wy1, Wz0, Wz1, wx;
};

__device__ __forceinline__ Setup
make_setup(float4 v, int x, int y, int z, int sub)
{
    float zf = (float)z + v.x;
    float yf = (float)y + v.y;
    float xf = (float)x + v.z;

    int z0 = __float2int_rd(zf);
    int y0 = __float2int_rd(yf);
    int x0 = __float2int_rd(xf);
    float fz = zf - (float)z0;
    float fy = yf - (float)y0;
    float fx = xf - (float)x0;
    int z1 = z0 + 1, y1 = y0 + 1;

    Setup s;
    s.Wz0 = ((unsigned)z0 < (unsigned)D) ? (1.0f - fz) : 0.0f;
    s.Wz1 = ((unsigned)z1 < (unsigned)D) ? fz          : 0.0f;
    s.Wy0 = ((unsigned)y0 < (unsigned)H) ? (1.0f - fy) : 0.0f;
    s.Wy1 = ((unsigned)y1 < (unsigned)H) ? fy          : 0.0f;
    float Wx0 = ((unsigned)x0 < (unsigned)W) ? (1.0f - fx) : 0.0f;
    float Wx1 = ((unsigned)(x0 + 1) < (unsigned)W) ? fx    : 0.0f;

    int zc0 = min(max(z0, 0), D - 1), zc1 = min(max(z1, 0), D - 1);
    int yc0 = min(max(y0, 0), H - 1), yc1 = min(max(y1, 0), H - 1);
    int xc0 = min(max(x0, 0), W - 1), xc1 = min(max(x0 + 1, 0), W - 1);

    int   xc = sub ? xc1 : xc0;
    s.wx     = sub ? Wx1 : Wx0;

    s.r00 = (zc0 * H + yc0) * W + xc;
    s.r01 = (zc0 * H + yc1) * W + xc;
    s.r10 = (zc1 * H + yc0) * W + xc;
    s.r11 = (zc1 * H + yc1) * W + xc;
    return s;
}

__device__ __forceinline__ float3
blend(const Setup& s, float4 c00, float4 c01, float4 c10, float4 c11)
{
    float3 p;
    {
        float a0 = fmaf(c01.x, s.Wy1, c00.x * s.Wy0);
        float a1 = fmaf(c11.x, s.Wy1, c10.x * s.Wy0);
        p.x = s.wx * fmaf(a1, s.Wz1, a0 * s.Wz0);
    }
    {
        float a0 = fmaf(c01.y, s.Wy1, c00.y * s.Wy0);
        float a1 = fmaf(c11.y, s.Wy1, c10.y * s.Wy0);
        p.y = s.wx * fmaf(a1, s.Wz1, a0 * s.Wz0);
    }
    {
        float a0 = fmaf(c01.z, s.Wy1, c00.z * s.Wy0);
        float a1 = fmaf(c11.z, s.Wy1, c10.z * s.Wy0);
        p.z = s.wx * fmaf(a1, s.Wz1, a0 * s.Wz0);
    }
    return p;
}

// One x-row pair per block: blockIdx.x = y, blockIdx.y = z (z < D/2);
// thread handles voxels (x,y,z) and (x,y,z+80). 320 threads = 160 vox * 2.
template<bool LAST>
__global__ void __launch_bounds__(320)
integrate_kernel(const float4* __restrict__ in, float4* __restrict__ out4,
                 float* __restrict__ out_soa)
{
    int x   = threadIdx.x >> 1;
    int sub = threadIdx.x & 1;
    int y   = blockIdx.x;
    int z   = blockIdx.y;              // [0, 80)
    int idxA = (z * H + y) * W + x;
    int idxB = idxA + ZOFF;

    float4 vA = in[idxA];
    float4 vB = in[idxB];

    Setup sA = make_setup(vA, x, y, z, sub);
    Setup sB = make_setup(vB, x, y, z + ZHALF, sub);

    // 8 independent gathers in flight
    float4 a00 = in[sA.r00];
    float4 a01 = in[sA.r01];
    float4 a10 = in[sA.r10];
    float4 a11 = in[sA.r11];
    float4 b00 = in[sB.r00];
    float4 b01 = in[sB.r01];
    float4 b10 = in[sB.r10];
    float4 b11 = in[sB.r11];

    float3 pA = blend(sA, a00, a01, a10, a11);
    float3 pB = blend(sB, b00, b01, b10, b11);

    pA.x += __shfl_xor_sync(0xFFFFFFFFu, pA.x, 1);
    pA.y += __shfl_xor_sync(0xFFFFFFFFu, pA.y, 1);
    pA.z += __shfl_xor_sync(0xFFFFFFFFu, pA.z, 1);
    pB.x += __shfl_xor_sync(0xFFFFFFFFu, pB.x, 1);
    pB.y += __shfl_xor_sync(0xFFFFFFFFu, pB.y, 1);
    pB.z += __shfl_xor_sync(0xFFFFFFFFu, pB.z, 1);

    if (sub == 0) {
        if (!LAST) {
            out4[idxA] = make_float4(vA.x + pA.x, vA.y + pA.y, vA.z + pA.z, 0.0f);
            out4[idxB] = make_float4(vB.x + pB.x, vB.y + pB.y, vB.z + pB.z, 0.0f);
        } else {
            out_soa[idxA]            = (vA.x + pA.x) * (1.0f / (0.5f * (D - 1)));
            out_soa[idxA + NVOX]     = (vA.y + pA.y) * (1.0f / (0.5f * (H - 1)));
            out_soa[idxA + 2 * NVOX] = (vA.z + pA.z) * (1.0f / (0.5f * (W - 1)));
            out_soa[idxB]            = (vB.x + pB.x) * (1.0f / (0.5f * (D - 1)));
            out_soa[idxB + NVOX]     = (vB.y + pB.y) * (1.0f / (0.5f * (H - 1)));
            out_soa[idxB + 2 * NVOX] = (vB.z + pB.z) * (1.0f / (0.5f * (W - 1)));
        }
    }
}

extern "C" void kernel_launch(void* const* d_in, const int* in_sizes, int n_in,
                              void* d_out, int out_size)
{
    const float* vec = (const float*)d_in[0];
    float* out = (float*)d_out;

    float4 *bufA, *bufB;
    cudaGetSymbolAddress((void**)&bufA, g_bufA);
    cudaGetSymbolAddress((void**)&bufB, g_bufB);

    const int blocks_scale = NVOX / (256 * 4);    // 4800
    dim3 grid_int(H, ZHALF);                      // y, z-half
    const int threads_int = 2 * W;                // 320

    scale_in_kernel<<<blocks_scale, 256>>>(vec, bufA);

    float4* cur = bufA;
    float4* nxt = bufB;
    for (int i = 0; i < NSTEPS - 1; ++i) {
        integrate_kernel<false><<<grid_int, threads_int>>>(cur, nxt, nullptr);
        float4* tmp = cur; cur = nxt; nxt = tmp;
    }
    integrate_kernel<true><<<grid_int, threads_int>>>(cur, nullptr, out);
}

// round 7
// speedup vs baseline: 1.0157x; 1.0157x over previous
#include <cuda_runtime.h>

// VecInt: scaling-and-squaring integration of a stationary velocity field.
// vec (1,3,160,192,160) fp32, nsteps=7.
//
// Round 7: fuse scale_in into iteration 1. Iter-1 displacements are tiny
// (sigma ~0.62 voxel), so its gathers are nearly coalesced even from the SoA
// input; reading SoA directly and applying the per-channel scale at the
// gather is bit-identical to scale-then-gather (per-element multiply
// distributes). Deletes a full 217MB streaming pass. Iterations 2-7 keep the
// proven R5 pair-lane scheme (doubly pinned on L1tex wavefronts + LTS sector
// bandwidth at ~72us/iter; all restructurings proved neutral in R3/R6).

constexpr int D = 160;
constexpr int H = 192;
constexpr int W = 160;
constexpr int NVOX = D * H * W;          // 4,915,200
constexpr int NSTEPS = 7;

__device__ __align__(128) float4 g_bufA[NVOX];
__device__ __align__(128) float4 g_bufB[NVOX];

// ---------------------------------------------------------------------------
// Iteration 1, fused with SoA ingest + per-channel voxel-unit scaling.
// One thread per voxel, block = one x-row (160 threads), grid = (H, D).
// Numerically identical to scale_in followed by the R5 integrate step.
// ---------------------------------------------------------------------------
__global__ void __launch_bounds__(160)
iter1_kernel(const float* __restrict__ in, float4* __restrict__ out)
{
    int x = threadIdx.x;
    int y = blockIdx.x;
    int z = blockIdx.y;
    int idx = (z * H + y) * W + x;

    const float s  = 1.0f / 128.0f;          // 1/2^7
    const float sD = s * 0.5f * (D - 1);     // channel 0 (z-displacement)
    const float sH = s * 0.5f * (H - 1);     // channel 1 (y)
    const float sW = s * 0.5f * (W - 1);     // channel 2 (x)

    const float* p0 = in;                // channel 0 plane
    const float* p1 = in + NVOX;         // channel 1 plane
    const float* p2 = in + 2 * NVOX;     // channel 2 plane

    float vx = p0[idx] * sD;
    float vy = p1[idx] * sH;
    float vz = p2[idx] * sW;

    float zf = (float)z + vx;
    float yf = (float)y + vy;
    float xf = (float)x + vz;

    int z0 = __float2int_rd(zf);
    int y0 = __float2int_rd(yf);
    int x0 = __float2int_rd(xf);
    float fz = zf - (float)z0;
    float fy = yf - (float)y0;
    float fx = xf - (float)x0;
    int z1 = z0 + 1, y1 = y0 + 1;

    float Wz0 = ((unsigned)z0 < (unsigned)D) ? (1.0f - fz) : 0.0f;
    float Wz1 = ((unsigned)z1 < (unsigned)D) ? fz          : 0.0f;
    float Wy0 = ((unsigned)y0 < (unsigned)H) ? (1.0f - fy) : 0.0f;
    float Wy1 = ((unsigned)y1 < (unsigned)H) ? fy          : 0.0f;
    float Wx0 = ((unsigned)x0 < (unsigned)W) ? (1.0f - fx) : 0.0f;
    float Wx1 = ((unsigned)(x0 + 1) < (unsigned)W) ? fx    : 0.0f;

    int zc0 = min(max(z0, 0), D - 1), zc1 = min(max(z1, 0), D - 1);
    int yc0 = min(max(y0, 0), H - 1), yc1 = min(max(y1, 0), H - 1);
    int xc0 = min(max(x0, 0), W - 1), xc1 = min(max(x0 + 1, 0), W - 1);

    int r00 = (zc0 * H + yc0) * W;
    int r01 = (zc0 * H + yc1) * W;
    int r10 = (zc1 * H + yc0) * W;
    int r11 = (zc1 * H + yc1) * W;

    // per-channel: gather 8 raw corners, scale, blend in the exact R5 order
    // (z/y blend, multiply by this-x weight, then sum x0-part + x1-part).
    float px, py, pz;
    {
        const float* p = p0; const float sc = sD;
        float c00a = p[r00 + xc0] * sc, c00b = p[r00 + xc1] * sc;
        float c01a = p[r01 + xc0] * sc, c01b = p[r01 + xc1] * sc;
        float c10a = p[r10 + xc0] * sc, c10b = p[r10 + xc1] * sc;
        float c11a = p[r11 + xc0] * sc, c11b = p[r11 + xc1] * sc;
        float a0A = fmaf(c01a, Wy1, c00a * Wy0);
        float a1A = fmaf(c11a, Wy1, c10a * Wy0);
        float a0B = fmaf(c01b, Wy1, c00b * Wy0);
        float a1B = fmaf(c11b, Wy1, c10b * Wy0);
        px = Wx0 * fmaf(a1A, Wz1, a0A * Wz0)
           + Wx1 * fmaf(a1B, Wz1, a0B * Wz0);
    }
    {
        const float* p = p1; const float sc = sH;
        float c00a = p[r00 + xc0] * sc, c00b = p[r00 + xc1] * sc;
        float c01a = p[r01 + xc0] * sc, c01b = p[r01 + xc1] * sc;
        float c10a = p[r10 + xc0] * sc, c10b = p[r10 + xc1] * sc;
        float c11a = p[r11 + xc0] * sc, c11b = p[r11 + xc1] * sc;
        float a0A = fmaf(c01a, Wy1, c00a * Wy0);
        float a1A = fmaf(c11a, Wy1, c10a * Wy0);
        float a0B = fmaf(c01b, Wy1, c00b * Wy0);
        float a1B = fmaf(c11b, Wy1, c10b * Wy0);
        py = Wx0 * fmaf(a1A, Wz1, a0A * Wz0)
           + Wx1 * fmaf(a1B, Wz1, a0B * Wz0);
    }
    {
        const float* p = p2; const float sc = sW;
        float c00a = p[r00 + xc0] * sc, c00b = p[r00 + xc1] * sc;
        float c01a = p[r01 + xc0] * sc, c01b = p[r01 + xc1] * sc;
        float c10a = p[r10 + xc0] * sc, c10b = p[r10 + xc1] * sc;
        float c11a = p[r11 + xc0] * sc, c11b = p[r11 + xc1] * sc;
        float a0A = fmaf(c01a, Wy1, c00a * Wy0);
        float a1A = fmaf(c11a, Wy1, c10a * Wy0);
        float a0B = fmaf(c01b, Wy1, c00b * Wy0);
        float a1B = fmaf(c11b, Wy1, c10b * Wy0);
        pz = Wx0 * fmaf(a1A, Wz1, a0A * Wz0)
           + Wx1 * fmaf(a1B, Wz1, a0B * Wz0);
    }

    out[idx] = make_float4(vx + px, vy + py, vz + pz, 0.0f);
}

// ---------------------------------------------------------------------------
// Iterations 2-7: R5 pair-lane scheme. One x-row per block, 320 threads =
// 160 voxels * 2 lanes; even lane takes x0 corners, odd lane x1.
// ---------------------------------------------------------------------------
template<bool LAST>
__global__ void __launch_bounds__(320)
integrate_kernel(const float4* __restrict__ in, float4* __restrict__ out4,
                 float* __restrict__ out_soa)
{
    int x   = threadIdx.x >> 1;
    int sub = threadIdx.x & 1;
    int y   = blockIdx.x;
    int z   = blockIdx.y;
    int idx = (z * H + y) * W + x;

    float4 v = in[idx];   // same address in both pair lanes -> broadcast

    float zf = (float)z + v.x;
    float yf = (float)y + v.y;
    float xf = (float)x + v.z;

    int z0 = __float2int_rd(zf);
    int y0 = __float2int_rd(yf);
    int x0 = __float2int_rd(xf);
    float fz = zf - (float)z0;
    float fy = yf - (float)y0;
    float fx = xf - (float)x0;
    int z1 = z0 + 1, y1 = y0 + 1;

    float Wz0 = ((unsigned)z0 < (unsigned)D) ? (1.0f - fz) : 0.0f;
    float Wz1 = ((unsigned)z1 < (unsigned)D) ? fz          : 0.0f;
    float Wy0 = ((unsigned)y0 < (unsigned)H) ? (1.0f - fy) : 0.0f;
    float Wy1 = ((unsigned)y1 < (unsigned)H) ? fy          : 0.0f;
    float Wx0 = ((unsigned)x0 < (unsigned)W) ? (1.0f - fx) : 0.0f;
    float Wx1 = ((unsigned)(x0 + 1) < (unsigned)W) ? fx    : 0.0f;

    int zc0 = min(max(z0, 0), D - 1), zc1 = min(max(z1, 0), D - 1);
    int yc0 = min(max(y0, 0), H - 1), yc1 = min(max(y1, 0), H - 1);
    int xc0 = min(max(x0, 0), W - 1), xc1 = min(max(x0 + 1, 0), W - 1);

    int   xc = sub ? xc1 : xc0;
    float wx = sub ? Wx1 : Wx0;

    int r00 = (zc0 * H + yc0) * W + xc;
    int r01 = (zc0 * H + yc1) * W + xc;
    int r10 = (zc1 * H + yc0) * W + xc;
    int r11 = (zc1 * H + yc1) * W + xc;

    float4 c00 = in[r00];
    float4 c01 = in[r01];
    float4 c10 = in[r10];
    float4 c11 = in[r11];

    float px, py, pz;
    {
        float a0 = fmaf(c01.x, Wy1, c00.x * Wy0);
        float a1 = fmaf(c11.x, Wy1, c10.x * Wy0);
        px = wx * fmaf(a1, Wz1, a0 * Wz0);
    }
    {
        float a0 = fmaf(c01.y, Wy1, c00.y * Wy0);
        float a1 = fmaf(c11.y, Wy1, c10.y * Wy0);
        py = wx * fmaf(a1, Wz1, a0 * Wz0);
    }
    {
        float a0 = fmaf(c01.z, Wy1, c00.z * Wy0);
        float a1 = fmaf(c11.z, Wy1, c10.z * Wy0);
        pz = wx * fmaf(a1, Wz1, a0 * Wz0);
    }
    px += __shfl_xor_sync(0xFFFFFFFFu, px, 1);
    py += __shfl_xor_sync(0xFFFFFFFFu, py, 1);
    pz += __shfl_xor_sync(0xFFFFFFFFu, pz, 1);

    if (sub == 0) {
        if (!LAST) {
            float4 r;
            r.x = v.x + px;
            r.y = v.y + py;
            r.z = v.z + pz;
            r.w = 0.0f;
            out4[idx] = r;
        } else {
            out_soa[idx]            = (v.x + px) * (1.0f / (0.5f * (D - 1)));
            out_soa[idx + NVOX]     = (v.y + py) * (1.0f / (0.5f * (H - 1)));
            out_soa[idx + 2 * NVOX] = (v.z + pz) * (1.0f / (0.5f * (W - 1)));
        }
    }
}

extern "C" void kernel_launch(void* const* d_in, const int* in_sizes, int n_in,
                              void* d_out, int out_size)
{
    const float* vec = (const float*)d_in[0];
    float* out = (float*)d_out;

    float4 *bufA, *bufB;
    cudaGetSymbolAddress((void**)&bufA, g_bufA);
    cudaGetSymbolAddress((void**)&bufB, g_bufB);

    dim3 grid(H, D);                 // (y, z)

    // iteration 1, fused with ingest/scaling
    iter1_kernel<<<grid, W>>>(vec, bufA);

    // iterations 2..6
    float4* cur = bufA;
    float4* nxt = bufB;
    for (int i = 0; i < NSTEPS - 2; ++i) {
        integrate_kernel<false><<<grid, 2 * W>>>(cur, nxt, nullptr);
        float4* tmp = cur; cur = nxt; nxt = tmp;
    }
    // iteration 7, fused with SoA scale-out
    integrate_kernel<true><<<grid, 2 * W>>>(cur, nullptr, out);
}